// round 12
// baseline (speedup 1.0000x reference)
#include <cuda_runtime.h>
#include <cuda_fp16.h>
#include <cstdint>
#include <cstring>

// Problem constants
#define BB 2
#define QQ 10
#define CC 64
#define HH 256
#define WW 256
#define HWXY (HH * WW)            // 65536
#define KK 9
#define LL 64800                  // 180*360
#define NN (QQ * HWXY)            // 655360 per-b
#define BQ (BB * QQ)              // 20

// fp16 channel-last scratch: row n holds 64 halfs (128B) = 8 uint4
__device__ uint4  g_xt16[(size_t)BQ * HWXY * 8];     // 167.8 MB
// per-n channel stats (mean, max) in fp32
__device__ float2 g_stats[(size_t)BQ * HWXY];        // 10.5 MB
// per-(b,l) record: [n0..n8, gatebits0..8, pad, pad]  (20 uints = 80B)
__device__ uint4  g_rec[(size_t)BB * LL * 5];        // 10.4 MB

__device__ __forceinline__ unsigned h2u(__half2 h) {
    unsigned u;
    memcpy(&u, &h, 4);
    return u;
}

// ---------------------------------------------------------------------------
// Kernel 1: transpose + stats, coalesced on BOTH gmem sides.
// Warp w owns channel rows c = 8w..8w+7 across the block's 128 hw:
//   each LDG.128 covers one row x 128 hw = 512B contiguous (4 wavefronts).
// Thread then holds 8 c-values for its 4 hw -> packs 4 uint4 in registers,
// stats partials in registers. smem used only to swap the g-dimension across
// warps: 4 STS.128 + 4 LDS.128 + 4 coalesced STG.128 per thread.
// block 256 = 8 warps; block covers 128 hw; grid (HW/128 = 512, 1, BQ)
// ---------------------------------------------------------------------------
__global__ void __launch_bounds__(256)
transpose_stats_kernel(const float* __restrict__ x,
                       uint4* __restrict__ xt,
                       float2* __restrict__ stats)
{
    __shared__ __align__(16) uint4  s_xt[128][9];   // pad 9: de-conflict STS
    __shared__ __align__(16) float2 s_st[128][8];

    const int tid  = threadIdx.x;
    const int warp = tid >> 5;      // = g (channel group): c = 8*warp + i
    const int lane = tid & 31;
    const int bq   = blockIdx.z;
    const int hw0  = blockIdx.x * 128;

    // 8 perfectly coalesced row loads (512B per warp per LDG), streaming
    const size_t inbase = (size_t)bq * CC * HWXY + hw0 + lane * 4;
    float4 v[8];
    #pragma unroll
    for (int i = 0; i < 8; i++)
        v[i] = __ldcs((const float4*)&x[inbase + (size_t)(8 * warp + i) * HWXY]);

    // pack + stats partials, all in registers
    const float* vf = (const float*)v;   // vf[i*4 + j] = row 8w+i, hw lane*4+j
    #pragma unroll
    for (int j = 0; j < 4; j++) {
        float s = vf[j], m = vf[j];
        #pragma unroll
        for (int i = 1; i < 8; i++) {
            const float t = vf[i * 4 + j];
            s += t;
            m  = fmaxf(m, t);
        }
        uint4 u;
        u.x = h2u(__floats2half2_rn(vf[0 * 4 + j], vf[1 * 4 + j]));
        u.y = h2u(__floats2half2_rn(vf[2 * 4 + j], vf[3 * 4 + j]));
        u.z = h2u(__floats2half2_rn(vf[4 * 4 + j], vf[5 * 4 + j]));
        u.w = h2u(__floats2half2_rn(vf[6 * 4 + j], vf[7 * 4 + j]));
        const int hw = lane * 4 + j;
        s_xt[hw][warp] = u;
        s_st[hw][warp] = make_float2(s, m);
    }
    __syncthreads();

    // data out: 1024 uint4 in linear (hw,g) order -> 512B coalesced runs
    const size_t outbase = ((size_t)bq * HWXY + hw0) * 8;
    #pragma unroll
    for (int r = tid; r < 1024; r += 256)
        xt[outbase + r] = s_xt[r >> 3][r & 7];

    // stats out: fold the 8 warp-partials per hw, coalesced 8B stores
    if (tid < 128) {
        const float4* p = (const float4*)&s_st[tid][0];  // (s,m,s,m) x4
        const float4 a = p[0], b = p[1], c = p[2], d = p[3];
        const float s = a.x + a.z + b.x + b.z + c.x + c.z + d.x + d.z;
        const float m = fmaxf(fmaxf(fmaxf(a.y, a.w), fmaxf(b.y, b.w)),
                              fmaxf(fmaxf(c.y, c.w), fmaxf(d.y, d.w)));
        stats[(size_t)bq * HWXY + hw0 + tid] = make_float2(s * (1.0f / 64.0f), m);
    }
}

// ---------------------------------------------------------------------------
// Kernel 2: gate precompute. One thread per (b,l): read idx + stats, compute
// all 9 (1+sigmoid) gates, write packed record [n0..8, gate0..8, pad2].
// grid ((BB*LL+255)/256), block 256
// ---------------------------------------------------------------------------
__global__ void __launch_bounds__(256)
gate_kernel(const float2* __restrict__ stats,
            const void* __restrict__ idx_raw,   // (64800,9) int32 OR int64
            const float* __restrict__ att_w,    // (9,2,9)
            const float* __restrict__ att_b,    // (9,)
            unsigned* __restrict__ rec)         // (BB*LL, 20) uints
{
    __shared__ float s_aw[KK * 2 * KK];
    __shared__ float s_ab[KK];
    const int tid = threadIdx.x;
    if (tid < KK * 2 * KK) s_aw[tid] = att_w[tid];
    if (tid < KK)          s_ab[tid] = att_b[tid];
    __syncthreads();

    const int gid = blockIdx.x * 256 + tid;
    if (gid >= BB * LL) return;
    const int b = gid / LL;
    const int l = gid - b * LL;

    // dtype sniff: int64 values < 2^31 have zero high words at odd 32-bit slots
    const int* __restrict__ i32 = (const int*)idx_raw;
    const bool is64 = (i32[1] | i32[3] | i32[5] | i32[7] |
                       i32[9] | i32[11] | i32[13] | i32[15]) == 0;

    int n[KK];
    #pragma unroll
    for (int k = 0; k < KK; k++) {
        const size_t pos = (size_t)l * KK + k;
        n[k] = is64 ? (int)((const long long*)idx_raw)[pos] : i32[pos];
    }

    float mn[KK], mx[KK];
    #pragma unroll
    for (int k = 0; k < KK; k++) {
        const float2 st = __ldg(&stats[(size_t)b * NN + n[k]]);
        mn[k] = st.x;
        mx[k] = st.y;
    }

    unsigned r[20];
    #pragma unroll
    for (int k = 0; k < KK; k++) r[k] = (unsigned)n[k];
    #pragma unroll
    for (int i = 0; i < KK; i++) {
        float z = s_ab[i];
        #pragma unroll
        for (int k = 0; k < KK; k++) {
            z = fmaf(mn[k], s_aw[i * 18 + k],     z);
            z = fmaf(mx[k], s_aw[i * 18 + 9 + k], z);
        }
        const float gte = 1.0f + 1.0f / (1.0f + __expf(-z));
        r[KK + i] = __float_as_uint(gte);
    }
    r[18] = 0; r[19] = 0;

    uint4* __restrict__ rec4 = (uint4*)rec;
    const size_t base = (size_t)gid * 5;
    #pragma unroll
    for (int q = 0; q < 5; q++)
        rec4[base + q] = make_uint4(r[q*4], r[q*4+1], r[q*4+2], r[q*4+3]);
}

// ---------------------------------------------------------------------------
// Kernel 3: gather + contraction only. Per l: one record load + 18 shfl +
// 9 gather LDG + 18 FMA. block 256 = 8 warps x 4 l = 32 consecutive l.
// grid: (LL/32 = 2025, BB)
// ---------------------------------------------------------------------------
__global__ void __launch_bounds__(256)
fused_kernel(const uint* __restrict__ xt16,      // half2 view of scratch
             const unsigned* __restrict__ rec,   // (BB*LL, 20)
             const float* __restrict__ tc_w,     // (64,9)
             const float* __restrict__ tc_b,     // (64,)
             float* __restrict__ out)            // (B, 64, L)
{
    __shared__ __align__(16) float s_out[CC][36];

    const int tid  = threadIdx.x;
    const int warp = tid >> 5;
    const int lane = tid & 31;
    const int b    = blockIdx.y;
    const int lblk = blockIdx.x * 32;
    const int c0   = lane * 2;

    float w0[KK], w1[KK];
    #pragma unroll
    for (int k = 0; k < KK; k++) {
        w0[k] = __ldg(&tc_w[c0 * KK + k]);
        w1[k] = __ldg(&tc_w[(c0 + 1) * KK + k]);
    }
    const float bias0 = __ldg(&tc_b[c0]);
    const float bias1 = __ldg(&tc_b[c0 + 1]);

    #pragma unroll
    for (int j = 0; j < 4; j++) {
        const int l  = lblk + warp * 4 + j;
        const int ll = warp * 4 + j;

        // one 72B record read: lanes 0..8 -> n, lanes 9..17 -> gate
        unsigned r = 0;
        if (lane < 18) r = rec[((size_t)b * LL + l) * 20 + lane];

        // broadcast indices, issue all gathers immediately (stay in flight)
        int n[KK];
        #pragma unroll
        for (int k = 0; k < KK; k++)
            n[k] = (int)__shfl_sync(0xffffffffu, r, k);

        uint vu[KK];
        #pragma unroll
        for (int k = 0; k < KK; k++)
            vu[k] = xt16[((size_t)b * NN + (size_t)n[k]) * 32 + lane];

        float o0 = bias0, o1 = bias1;
        #pragma unroll
        for (int k = 0; k < KK; k++) {
            const float sc = __uint_as_float(__shfl_sync(0xffffffffu, r, KK + k));
            const float2 v = __half22float2(*(const __half2*)&vu[k]);
            o0 = fmaf(v.x * sc, w0[k], o0);
            o1 = fmaf(v.y * sc, w1[k], o1);
        }

        s_out[c0][ll]     = o0;
        s_out[c0 + 1][ll] = o1;
    }
    __syncthreads();

    // Coalesced output: 64 rows x 8 float4, full 128B lines
    #pragma unroll
    for (int s = tid; s < 512; s += 256) {
        const int c = s >> 3;
        const int q = s & 7;
        const float4 vv = *(const float4*)&s_out[c][q * 4];
        *(float4*)&out[((size_t)(b * CC + c)) * LL + lblk + q * 4] = vv;
    }
}

// ---------------------------------------------------------------------------
extern "C" void kernel_launch(void* const* d_in, const int* in_sizes, int n_in,
                              void* d_out, int out_size)
{
    const float* x     = (const float*)d_in[0];      // (20, 64, 256, 256)
    const void*  idx   = d_in[1];                    // (64800, 9) int32 or int64
    const float* att_w = (const float*)d_in[2];      // (9,2,9)
    const float* att_b = (const float*)d_in[3];      // (9,)
    const float* tc_w  = (const float*)d_in[4];      // (64,9)
    const float* tc_b  = (const float*)d_in[5];      // (64,)
    float*       out   = (float*)d_out;              // (2, 64, 180, 360)

    uint4* xt;  float2* stats;  uint4* rec;
    cudaGetSymbolAddress((void**)&xt, g_xt16);
    cudaGetSymbolAddress((void**)&stats, g_stats);
    cudaGetSymbolAddress((void**)&rec, g_rec);

    {
        dim3 grid(HWXY / 128, 1, BQ);
        transpose_stats_kernel<<<grid, 256>>>(x, xt, stats);
    }
    {
        dim3 grid((BB * LL + 255) / 256);
        gate_kernel<<<grid, 256>>>(stats, idx, att_w, att_b, (unsigned*)rec);
    }
    {
        dim3 grid(LL / 32, BB);
        fused_kernel<<<grid, 256>>>((const uint*)xt, (const unsigned*)rec,
                                    tc_w, tc_b, out);
    }
}